// round 2
// baseline (speedup 1.0000x reference)
#include <cuda_runtime.h>
#include <cstdint>

// Problem constants
#define BB    128
#define LL    9
#define KK    3
#define PP    1680
#define CIN   256
#define COUT  256
#define ZR    1152
#define ZC    768

// Scratch (device globals: allocation-free)
__device__ float g_Z[ZR * ZC];                 // 3.4 MB   (B*L, K*COUT)
__device__ float4 g_T[BB * 81 * 64];           // 10.6 MB  T[b][cc=g*27+c][o4]
__device__ int    g_codes[PP];

// ---------------------------------------------------------------------------
// Kernel 1: Z[r,j] = sum_c X[r,c] * Wm[j,c]
// 64x64 tile, K-chunks of 64, transposed smem tiles, 4x4 reg tile/thread.
// ---------------------------------------------------------------------------
__global__ void __launch_bounds__(256) gemm_z(const float* __restrict__ X,
                                              const float* __restrict__ Wm) {
    __shared__ float sXt[64][68];
    __shared__ float sWt[64][68];

    const int t  = threadIdx.x;
    const int rb = blockIdx.x * 64;
    const int jb = blockIdx.y * 64;

    const int c4 = t & 15;
    const int rr = t >> 4;

    float acc[4][4];
#pragma unroll
    for (int i = 0; i < 4; i++)
#pragma unroll
        for (int j = 0; j < 4; j++) acc[i][j] = 0.0f;

    const int row0 = (t >> 4) * 4;
    const int col0 = (t & 15) * 4;

    for (int kc = 0; kc < CIN; kc += 64) {
#pragma unroll
        for (int i = 0; i < 4; i++) {
            int r = rr + i * 16;
            float4 v = *(const float4*)&X[(rb + r) * CIN + kc + c4 * 4];
            sXt[c4 * 4 + 0][r] = v.x;
            sXt[c4 * 4 + 1][r] = v.y;
            sXt[c4 * 4 + 2][r] = v.z;
            sXt[c4 * 4 + 3][r] = v.w;
            float4 w = *(const float4*)&Wm[(jb + r) * CIN + kc + c4 * 4];
            sWt[c4 * 4 + 0][r] = w.x;
            sWt[c4 * 4 + 1][r] = w.y;
            sWt[c4 * 4 + 2][r] = w.z;
            sWt[c4 * 4 + 3][r] = w.w;
        }
        __syncthreads();

#pragma unroll
        for (int c = 0; c < 64; c++) {
            float4 xa = *(const float4*)&sXt[c][row0];
            float4 wb = *(const float4*)&sWt[c][col0];
            acc[0][0] += xa.x * wb.x; acc[0][1] += xa.x * wb.y;
            acc[0][2] += xa.x * wb.z; acc[0][3] += xa.x * wb.w;
            acc[1][0] += xa.y * wb.x; acc[1][1] += xa.y * wb.y;
            acc[1][2] += xa.y * wb.z; acc[1][3] += xa.y * wb.w;
            acc[2][0] += xa.z * wb.x; acc[2][1] += xa.z * wb.y;
            acc[2][2] += xa.z * wb.z; acc[2][3] += xa.z * wb.w;
            acc[3][0] += xa.w * wb.x; acc[3][1] += xa.w * wb.y;
            acc[3][2] += xa.w * wb.z; acc[3][3] += xa.w * wb.w;
        }
        __syncthreads();
    }

    float4* Z4 = (float4*)g_Z;
#pragma unroll
    for (int i = 0; i < 4; i++) {
        float4 v = make_float4(acc[i][0], acc[i][1], acc[i][2], acc[i][3]);
        Z4[(rb + row0 + i) * (ZC / 4) + (jb + col0) / 4] = v;
    }
}

// ---------------------------------------------------------------------------
// Kernel 2: build T[b][cc][o4] = sum_j Z[b, 3g+j, d_j(c), o4]  (Z hot in L2)
// and decode the permutation codes from M (fused; no separate launch).
// One block per b, 256 threads.
// ---------------------------------------------------------------------------
__global__ void __launch_bounds__(256) build_T(const float* __restrict__ M) {
    const int t = threadIdx.x;
    const int b = blockIdx.x;

    // fused code decode: block b handles p = b*14 .. b*14+13
    {
        int p = b * 14 + t;
        if (t < 14 && p < PP) {
            const int PL = PP * LL;
            int c[3] = {0, 0, 0};
            const int w3[3] = {1, 3, 9};
#pragma unroll
            for (int l = 0; l < LL; l++) {
                float m1 = M[PL + p * LL + l];
                float m2 = M[2 * PL + p * LL + l];
                int a = (m1 > 0.5f) ? 1 : ((m2 > 0.5f) ? 2 : 0);
                c[l / 3] += a * w3[l % 3];
            }
            g_codes[p] = c[0] | (c[1] << 8) | (c[2] << 16);
        }
    }

    const float4* Z4 = (const float4*)g_Z;
    const int zb = b * LL * KK * (COUT / 4);
    const int tb = b * 81 * 64;

#pragma unroll 2
    for (int i = t; i < 81 * 64; i += 256) {
        int o4 = i & 63;
        int cc = i >> 6;             // g*27 + c
        int g  = cc / 27;
        int c  = cc - g * 27;
        int d0 = c % 3, d1 = (c / 3) % 3, d2 = c / 9;
        int l  = 3 * g;
        float4 v0 = Z4[zb + ((l + 0) * 3 + d0) * (COUT / 4) + o4];
        float4 v1 = Z4[zb + ((l + 1) * 3 + d1) * (COUT / 4) + o4];
        float4 v2 = Z4[zb + ((l + 2) * 3 + d2) * (COUT / 4) + o4];
        float4 s;
        s.x = v0.x + v1.x + v2.x;
        s.y = v0.y + v1.y + v2.y;
        s.z = v0.z + v1.z + v2.z;
        s.w = v0.w + v1.w + v2.w;
        g_T[tb + i] = s;
    }
}

// ---------------------------------------------------------------------------
// Kernel 3: combine. Stage this block's 81x32-float4 table slice from L2 into
// smem (plain copy), then each output float4 = T0[c0]+T1[c1]+T2[c2], streamed.
// grid = (5 p-chunks of 336, 2 channel halves, 128 b), 256 threads.
// ---------------------------------------------------------------------------
#define PCHUNK 336
#define NCHUNK 5

__global__ void __launch_bounds__(256) perm_combine(float* __restrict__ out) {
    __shared__ float4 sT4[81 * 32];
    __shared__ int sCodes[PCHUNK];

    const int t     = threadIdx.x;
    const int chunk = blockIdx.x;
    const int h     = blockIdx.y;
    const int b     = blockIdx.z;
    const int pbase = chunk * PCHUNK;

    // stage table slice (coalesced 512B rows from L2-resident g_T)
    const int tb = b * 81 * 64 + h * 32;
#pragma unroll 2
    for (int i = t; i < 81 * 32; i += 256) {
        int cc = i >> 5;
        int o4 = i & 31;
        sT4[i] = g_T[tb + cc * 64 + o4];
    }
    for (int i = t; i < PCHUNK; i += 256) sCodes[i] = g_codes[pbase + i];
    __syncthreads();

    const int o4 = t & 31;
    const int pw = t >> 5;
    float4* out4 = (float4*)out;
    const int obase = (b * PP + pbase) * (COUT / 4) + h * 32 + o4;

#pragma unroll 2
    for (int it = 0; it < PCHUNK / 8; it++) {
        int po   = it * 8 + pw;
        int code = sCodes[po];
        int c0 = code & 0xFF;
        int c1 = (code >> 8) & 0xFF;
        int c2 = (code >> 16) & 0xFF;
        float4 a  = sT4[c0 * 32 + o4];
        float4 bb = sT4[(27 + c1) * 32 + o4];
        float4 cv = sT4[(54 + c2) * 32 + o4];
        float4 r;
        r.x = a.x + bb.x + cv.x;
        r.y = a.y + bb.y + cv.y;
        r.z = a.z + bb.z + cv.z;
        r.w = a.w + bb.w + cv.w;
        __stcs(&out4[obase + po * (COUT / 4)], r);
    }
}

// ---------------------------------------------------------------------------
extern "C" void kernel_launch(void* const* d_in, const int* in_sizes, int n_in,
                              void* d_out, int out_size) {
    (void)in_sizes; (void)n_in; (void)out_size;
    const float* x = (const float*)d_in[0];  // (128, 9, 256)
    const float* W = (const float*)d_in[1];  // (3, 256, 256)
    const float* M = (const float*)d_in[2];  // (3, 1680, 9)
    float* out = (float*)d_out;              // (128, 1680, 256)

    gemm_z<<<dim3(ZR / 64, ZC / 64), 256>>>(x, W);
    build_T<<<BB, 256>>>(M);
    perm_combine<<<dim3(NCHUNK, 2, BB), 256>>>(out);
}

// round 3
// speedup vs baseline: 1.1085x; 1.1085x over previous
#include <cuda_runtime.h>
#include <cstdint>

// Problem constants
#define BB    128
#define LL    9
#define KK    3
#define PP    1680
#define CIN   256
#define COUT  256
#define ZR    1152
#define ZC    768

// Scratch (device globals: allocation-free)
__device__ float g_Z[2 * ZR * ZC];             // 6.8 MB  two K-split halves
__device__ float4 g_T[BB * 81 * 64];           // 10.6 MB T[b][cc=g*27+c][o4]
__device__ int    g_codes[PP];

// ---------------------------------------------------------------------------
// Kernel 1: partial GEMM. Zs[ks][r,j] = sum_{c in ks*128..+128} X[r,c]*Wm[j,c]
// 64x64 tile, two 64-wide K-chunks, transposed smem tiles, 4x4 reg tile,
// register prefetch to hide LDS latency. grid = (18, 12, 2) = 432 blocks.
// ---------------------------------------------------------------------------
__global__ void __launch_bounds__(256) gemm_z(const float* __restrict__ X,
                                              const float* __restrict__ Wm) {
    __shared__ float sXt[64][68];
    __shared__ float sWt[64][68];

    const int t  = threadIdx.x;
    const int rb = blockIdx.x * 64;
    const int jb = blockIdx.y * 64;
    const int kb = blockIdx.z * 128;

    const int c4 = t & 15;
    const int rr = t >> 4;

    float acc[4][4];
#pragma unroll
    for (int i = 0; i < 4; i++)
#pragma unroll
        for (int j = 0; j < 4; j++) acc[i][j] = 0.0f;

    const int row0 = (t >> 4) * 4;
    const int col0 = (t & 15) * 4;

#pragma unroll
    for (int kk = 0; kk < 2; kk++) {
        const int kc = kb + kk * 64;
#pragma unroll
        for (int i = 0; i < 4; i++) {
            int r = rr + i * 16;
            float4 v = *(const float4*)&X[(rb + r) * CIN + kc + c4 * 4];
            sXt[c4 * 4 + 0][r] = v.x;
            sXt[c4 * 4 + 1][r] = v.y;
            sXt[c4 * 4 + 2][r] = v.z;
            sXt[c4 * 4 + 3][r] = v.w;
            float4 w = *(const float4*)&Wm[(jb + r) * CIN + kc + c4 * 4];
            sWt[c4 * 4 + 0][r] = w.x;
            sWt[c4 * 4 + 1][r] = w.y;
            sWt[c4 * 4 + 2][r] = w.z;
            sWt[c4 * 4 + 3][r] = w.w;
        }
        __syncthreads();

        // prefetch first fragments
        float4 xa = *(const float4*)&sXt[0][row0];
        float4 wb = *(const float4*)&sWt[0][col0];
#pragma unroll
        for (int c = 0; c < 64; c++) {
            float4 xc = xa, wc = wb;
            if (c < 63) {
                xa = *(const float4*)&sXt[c + 1][row0];
                wb = *(const float4*)&sWt[c + 1][col0];
            }
            acc[0][0] += xc.x * wc.x; acc[0][1] += xc.x * wc.y;
            acc[0][2] += xc.x * wc.z; acc[0][3] += xc.x * wc.w;
            acc[1][0] += xc.y * wc.x; acc[1][1] += xc.y * wc.y;
            acc[1][2] += xc.y * wc.z; acc[1][3] += xc.y * wc.w;
            acc[2][0] += xc.z * wc.x; acc[2][1] += xc.z * wc.y;
            acc[2][2] += xc.z * wc.z; acc[2][3] += xc.z * wc.w;
            acc[3][0] += xc.w * wc.x; acc[3][1] += xc.w * wc.y;
            acc[3][2] += xc.w * wc.z; acc[3][3] += xc.w * wc.w;
        }
        __syncthreads();
    }

    float4* Z4 = (float4*)(g_Z + blockIdx.z * (ZR * ZC));
#pragma unroll
    for (int i = 0; i < 4; i++) {
        float4 v = make_float4(acc[i][0], acc[i][1], acc[i][2], acc[i][3]);
        Z4[(rb + row0 + i) * (ZC / 4) + (jb + col0) / 4] = v;
    }
}

// ---------------------------------------------------------------------------
// Kernel 2: build T[b][cc][o4] = sum_j (Z0+Z1)[b, 3g+j, d_j(c), o4]
// + fused code decode from M. One block per b, 256 threads.
// ---------------------------------------------------------------------------
__global__ void __launch_bounds__(256) build_T(const float* __restrict__ M) {
    const int t = threadIdx.x;
    const int b = blockIdx.x;

    {
        int p = b * 14 + t;
        if (t < 14 && p < PP) {
            const int PL = PP * LL;
            int c[3] = {0, 0, 0};
            const int w3[3] = {1, 3, 9};
#pragma unroll
            for (int l = 0; l < LL; l++) {
                float m1 = M[PL + p * LL + l];
                float m2 = M[2 * PL + p * LL + l];
                int a = (m1 > 0.5f) ? 1 : ((m2 > 0.5f) ? 2 : 0);
                c[l / 3] += a * w3[l % 3];
            }
            g_codes[p] = c[0] | (c[1] << 8) | (c[2] << 16);
        }
    }

    const float4* Za = (const float4*)g_Z;
    const float4* Zb = (const float4*)(g_Z + ZR * ZC);
    const int zb = b * LL * KK * (COUT / 4);
    const int tb = b * 81 * 64;

#pragma unroll 2
    for (int i = t; i < 81 * 64; i += 256) {
        int o4 = i & 63;
        int cc = i >> 6;             // g*27 + c
        int g  = cc / 27;
        int c  = cc - g * 27;
        int d0 = c % 3, d1 = (c / 3) % 3, d2 = c / 9;
        int l  = 3 * g;
        int i0 = zb + ((l + 0) * 3 + d0) * (COUT / 4) + o4;
        int i1 = zb + ((l + 1) * 3 + d1) * (COUT / 4) + o4;
        int i2 = zb + ((l + 2) * 3 + d2) * (COUT / 4) + o4;
        float4 a0 = Za[i0], b0 = Zb[i0];
        float4 a1 = Za[i1], b1 = Zb[i1];
        float4 a2 = Za[i2], b2 = Zb[i2];
        float4 s;
        s.x = (a0.x + b0.x) + (a1.x + b1.x) + (a2.x + b2.x);
        s.y = (a0.y + b0.y) + (a1.y + b1.y) + (a2.y + b2.y);
        s.z = (a0.z + b0.z) + (a1.z + b1.z) + (a2.z + b2.z);
        s.w = (a0.w + b0.w) + (a1.w + b1.w) + (a2.w + b2.w);
        g_T[tb + i] = s;
    }
}

// ---------------------------------------------------------------------------
// Kernel 3: combine. Stage the 81x32-float4 table slice into smem (copy),
// then each output float4 = T0[c0]+T1[c1]+T2[c2], streamed to GMEM.
// grid = (5 p-chunks of 336, 2 channel halves, 128 b), 256 threads.
// ---------------------------------------------------------------------------
#define PCHUNK 336
#define NCHUNK 5

__global__ void __launch_bounds__(256) perm_combine(float* __restrict__ out) {
    __shared__ float4 sT4[81 * 32];
    __shared__ int sCodes[PCHUNK];

    const int t     = threadIdx.x;
    const int chunk = blockIdx.x;
    const int h     = blockIdx.y;
    const int b     = blockIdx.z;
    const int pbase = chunk * PCHUNK;

    const int tb = b * 81 * 64 + h * 32;
#pragma unroll 2
    for (int i = t; i < 81 * 32; i += 256) {
        int cc = i >> 5;
        int o4 = i & 31;
        sT4[i] = g_T[tb + cc * 64 + o4];
    }
    for (int i = t; i < PCHUNK; i += 256) sCodes[i] = g_codes[pbase + i];
    __syncthreads();

    const int o4 = t & 31;
    const int pw = t >> 5;
    float4* out4 = (float4*)out;
    const int obase = (b * PP + pbase) * (COUT / 4) + h * 32 + o4;

#pragma unroll 2
    for (int it = 0; it < PCHUNK / 8; it++) {
        int po   = it * 8 + pw;
        int code = sCodes[po];
        int c0 = code & 0xFF;
        int c1 = (code >> 8) & 0xFF;
        int c2 = (code >> 16) & 0xFF;
        float4 a  = sT4[c0 * 32 + o4];
        float4 bb = sT4[(27 + c1) * 32 + o4];
        float4 cv = sT4[(54 + c2) * 32 + o4];
        float4 r;
        r.x = a.x + bb.x + cv.x;
        r.y = a.y + bb.y + cv.y;
        r.z = a.z + bb.z + cv.z;
        r.w = a.w + bb.w + cv.w;
        __stcs(&out4[obase + po * (COUT / 4)], r);
    }
}

// ---------------------------------------------------------------------------
extern "C" void kernel_launch(void* const* d_in, const int* in_sizes, int n_in,
                              void* d_out, int out_size) {
    (void)in_sizes; (void)n_in; (void)out_size;
    const float* x = (const float*)d_in[0];  // (128, 9, 256)
    const float* W = (const float*)d_in[1];  // (3, 256, 256)
    const float* M = (const float*)d_in[2];  // (3, 1680, 9)
    float* out = (float*)d_out;              // (128, 1680, 256)

    gemm_z<<<dim3(ZR / 64, ZC / 64, 2), 256>>>(x, W);
    build_T<<<BB, 256>>>(M);
    perm_combine<<<dim3(NCHUNK, 2, BB), 256>>>(out);
}